// round 3
// baseline (speedup 1.0000x reference)
#include <cuda_runtime.h>
#include <math.h>

#define BB 128
#define TT 2048
#define HH 512
#define MM (BB*TT)

#define MT 128
#define NT 64
#define KT 32

// Scratch (device globals; no allocation allowed)
__device__ float g_Wsum[HH*HH];
__device__ float g_bsum[HH];
__device__ float g_score[MM];

// ---------------------------------------------------------------------------
// Packed f32x2 helpers (Blackwell: ptxas won't auto-fuse, must use PTX)
// ---------------------------------------------------------------------------
__device__ __forceinline__ void fma2(unsigned long long &d,
                                     unsigned long long a,
                                     unsigned long long b) {
    asm("fma.rn.f32x2 %0, %1, %2, %0;" : "+l"(d) : "l"(a), "l"(b));
}
__device__ __forceinline__ unsigned long long dup2(float v) {
    unsigned long long r;
    asm("mov.b64 %0, {%1, %1};" : "=l"(r) : "f"(v));
    return r;
}

// ---------------------------------------------------------------------------
// K1: Wsum = Wa_w + Ua_w ; bsum = Wa_b + Ua_b
// ---------------------------------------------------------------------------
__global__ void prep_kernel(const float* __restrict__ Wa_w,
                            const float* __restrict__ Wa_b,
                            const float* __restrict__ Ua_w,
                            const float* __restrict__ Ua_b) {
    int i = blockIdx.x * blockDim.x + threadIdx.x;
    if (i < HH * HH) g_Wsum[i] = Wa_w[i] + Ua_w[i];
    if (i < HH)      g_bsum[i] = Wa_b[i] + Ua_b[i];
}

// ---------------------------------------------------------------------------
// K2: fused score GEMM:
//   score[m] = sum_o v[o] * tanh( bsum[o] + sum_k X[m,k]*Wsum[o,k] )
// CTA tile: 128 (M) x 64 (N per block, 8 blocks) x K chunks of 32.
// Per-thread: 8m x 4o, accumulators f32x2 packed along M.
// ---------------------------------------------------------------------------
__global__ __launch_bounds__(256, 1)
void score_kernel(const float* __restrict__ X,
                  const float* __restrict__ Va_w) {
    __shared__ __align__(16) float Xs[KT][MT + 4];   // m-major rows, pad 4
    __shared__ __align__(16) float Ws[KT][NT + 4];   // o-major rows, pad 4

    const int tid = threadIdx.x;
    const int tx = tid & 15;          // o group
    const int ty = tid >> 4;          // m group
    const int m0 = ty * 8;
    const int o0 = tx * 4;
    const size_t m_base = (size_t)blockIdx.x * MT;

    float sp[8];
#pragma unroll
    for (int j = 0; j < 8; j++) sp[j] = 0.0f;

    // staging prefetch registers
    float4 xr[4];
    float4 wr[2];

    const int NCH = HH / KT;  // 16 K-chunks per N-block
    const int NOB = HH / NT;  // 8 N-blocks

    // load chunk (ob, kc) into registers
    auto load_regs = [&](int ob, int kc) {
        const int kb = kc * KT;
#pragma unroll
        for (int i = 0; i < 4; i++) {
            int u  = tid + i * 256;          // 0..1023 float4 units for X tile
            int m  = u >> 3;                 // 0..127
            int k4 = (u & 7) * 4;            // 0..28
            xr[i] = *(const float4*)(X + (m_base + m) * HH + kb + k4);
        }
#pragma unroll
        for (int i = 0; i < 2; i++) {
            int u  = tid + i * 256;          // 0..511 float4 units for W tile
            int o  = u >> 3;                 // 0..63
            int k4 = (u & 7) * 4;
            wr[i] = *(const float4*)(g_Wsum + (size_t)(ob * NT + o) * HH + kb + k4);
        }
    };

    auto store_smem = [&]() {
#pragma unroll
        for (int i = 0; i < 4; i++) {
            int u  = tid + i * 256;
            int m  = u >> 3;
            int k4 = (u & 7) * 4;
            Xs[k4 + 0][m] = xr[i].x;
            Xs[k4 + 1][m] = xr[i].y;
            Xs[k4 + 2][m] = xr[i].z;
            Xs[k4 + 3][m] = xr[i].w;
        }
#pragma unroll
        for (int i = 0; i < 2; i++) {
            int u  = tid + i * 256;
            int o  = u >> 3;
            int k4 = (u & 7) * 4;
            Ws[k4 + 0][o] = wr[i].x;
            Ws[k4 + 1][o] = wr[i].y;
            Ws[k4 + 2][o] = wr[i].z;
            Ws[k4 + 3][o] = wr[i].w;
        }
    };

    load_regs(0, 0);

    for (int ob = 0; ob < NOB; ob++) {
        unsigned long long acc[4][4];
#pragma unroll
        for (int mp = 0; mp < 4; mp++)
#pragma unroll
            for (int oi = 0; oi < 4; oi++) acc[mp][oi] = 0ull;

        for (int kc = 0; kc < NCH; kc++) {
            __syncthreads();         // previous compute done reading smem
            store_smem();
            __syncthreads();

            // prefetch next chunk while computing this one
            if (kc + 1 < NCH)      load_regs(ob, kc + 1);
            else if (ob + 1 < NOB) load_regs(ob + 1, 0);

#pragma unroll 8
            for (int k = 0; k < KT; k++) {
                ulonglong2 xa = *(const ulonglong2*)&Xs[k][m0];
                ulonglong2 xb = *(const ulonglong2*)&Xs[k][m0 + 4];
                float4 wv = *(const float4*)&Ws[k][o0];
                unsigned long long w0 = dup2(wv.x);
                unsigned long long w1 = dup2(wv.y);
                unsigned long long w2 = dup2(wv.z);
                unsigned long long w3 = dup2(wv.w);
                fma2(acc[0][0], xa.x, w0);
                fma2(acc[1][0], xa.y, w0);
                fma2(acc[2][0], xb.x, w0);
                fma2(acc[3][0], xb.y, w0);
                fma2(acc[0][1], xa.x, w1);
                fma2(acc[1][1], xa.y, w1);
                fma2(acc[2][1], xb.x, w1);
                fma2(acc[3][1], xb.y, w1);
                fma2(acc[0][2], xa.x, w2);
                fma2(acc[1][2], xa.y, w2);
                fma2(acc[2][2], xb.x, w2);
                fma2(acc[3][2], xb.y, w2);
                fma2(acc[0][3], xa.x, w3);
                fma2(acc[1][3], xa.y, w3);
                fma2(acc[2][3], xb.x, w3);
                fma2(acc[3][3], xb.y, w3);
            }
        }

        // epilogue: sp[m] += v[o] * tanh(pre[m,o] + bsum[o])
#pragma unroll
        for (int oi = 0; oi < 4; oi++) {
            int o = ob * NT + o0 + oi;
            float vo = __ldg(Va_w + o);
            float bo = g_bsum[o];
#pragma unroll
            for (int mp = 0; mp < 4; mp++) {
                unsigned long long a = acc[mp][oi];
                float lo = __uint_as_float((unsigned)(a & 0xffffffffull));
                float hi = __uint_as_float((unsigned)(a >> 32));
                sp[2 * mp]     += vo * tanhf(lo + bo);
                sp[2 * mp + 1] += vo * tanhf(hi + bo);
            }
        }
    }

    // reduce over the 16 tx lanes (same-m threads occupy one half-warp)
#pragma unroll
    for (int j = 0; j < 8; j++) {
        float v = sp[j];
#pragma unroll
        for (int off = 8; off > 0; off >>= 1)
            v += __shfl_down_sync(0xffffffffu, v, off, 16);
        if (tx == 0) g_score[m_base + m0 + j] = v;
    }
}

// ---------------------------------------------------------------------------
// K3: per-batch softmax over T; writes attention_weights
// (Va_b is a uniform shift -> softmax-invariant -> omitted)
// ---------------------------------------------------------------------------
__global__ void softmax_kernel(float* __restrict__ aw_out) {
    __shared__ float sh[TT];
    __shared__ float red[256];
    const int b = blockIdx.x;
    const int tid = threadIdx.x;
    const float* s = g_score + (size_t)b * TT;

    float mx = -1e30f;
    for (int t = tid; t < TT; t += 256) {
        float v = s[t];
        sh[t] = v;
        mx = fmaxf(mx, v);
    }
    red[tid] = mx;
    __syncthreads();
    for (int o = 128; o > 0; o >>= 1) {
        if (tid < o) red[tid] = fmaxf(red[tid], red[tid + o]);
        __syncthreads();
    }
    mx = red[0];
    __syncthreads();

    float sum = 0.0f;
    for (int t = tid; t < TT; t += 256) {
        float e = __expf(sh[t] - mx);
        sh[t] = e;
        sum += e;
    }
    red[tid] = sum;
    __syncthreads();
    for (int o = 128; o > 0; o >>= 1) {
        if (tid < o) red[tid] += red[tid + o];
        __syncthreads();
    }
    float inv = 1.0f / red[0];

    for (int t = tid; t < TT; t += 256)
        aw_out[(size_t)b * TT + t] = sh[t] * inv;
}

// ---------------------------------------------------------------------------
// K4: context[b,h] = sum_t aw[b,t] * X[b,t,h]   (streaming, DRAM-bound)
// ---------------------------------------------------------------------------
__global__ void context_kernel(const float* __restrict__ X,
                               const float* __restrict__ aw,
                               float* __restrict__ ctx) {
    const int blk = blockIdx.x;
    const int b  = blk >> 2;
    const int hb = blk & 3;
    const int h  = hb * 128 + threadIdx.x;
    const float* xp = X + (size_t)b * TT * HH + h;
    const float* a  = aw + (size_t)b * TT;

    float acc = 0.0f;
#pragma unroll 8
    for (int t = 0; t < TT; t++)
        acc += a[t] * xp[(size_t)t * HH];

    ctx[(size_t)b * HH + h] = acc;
}

// ---------------------------------------------------------------------------
// Launch: inputs in metadata order:
// lstm_output, Wa_w, Wa_b, Ua_w, Ua_b, Va_w, Va_b
// Output: [context (B*H) | attention_weights (B*T)]
// ---------------------------------------------------------------------------
extern "C" void kernel_launch(void* const* d_in, const int* in_sizes, int n_in,
                              void* d_out, int out_size) {
    const float* X    = (const float*)d_in[0];
    const float* Wa_w = (const float*)d_in[1];
    const float* Wa_b = (const float*)d_in[2];
    const float* Ua_w = (const float*)d_in[3];
    const float* Ua_b = (const float*)d_in[4];
    const float* Va_w = (const float*)d_in[5];
    // d_in[6] (Va_b) intentionally unused: softmax is shift-invariant.
    (void)in_sizes; (void)n_in; (void)out_size;

    float* out = (float*)d_out;
    float* ctx = out;                 // [B, H]
    float* aw  = out + BB * HH;       // [B, T]

    prep_kernel<<<(HH * HH + 255) / 256, 256>>>(Wa_w, Wa_b, Ua_w, Ua_b);
    score_kernel<<<MM / MT, 256>>>(X, Va_w);
    softmax_kernel<<<BB, 256>>>(aw);
    context_kernel<<<BB * 4, 128>>>(X, aw, ctx);
}

// round 5
// speedup vs baseline: 2.8736x; 2.8736x over previous
#include <cuda_runtime.h>
#include <cuda_bf16.h>
#include <cstdint>

#define BB 128
#define TT 2048
#define HH 512
#define MM (BB*TT)

// ---------------- device scratch (no allocations allowed) ----------------
__device__ __align__(16) __nv_bfloat16 g_Wh[HH*HH];
__device__ __align__(16) __nv_bfloat16 g_Wl[HH*HH];
__device__ __align__(16) float2 g_vb[HH];          // {v[o], bsum[o]*2*log2(e)}
__device__ float g_score[MM];
__device__ float g_cpart[4*BB*HH];

#define SW128(o) ((o) ^ (((o) >> 3) & 0x70))
#define TWO_LOG2E 2.885390081777927f

__device__ __forceinline__ uint32_t smem_u32(const void* p) {
    uint32_t a;
    asm("{ .reg .u64 t; cvta.to.shared.u64 t, %1; cvt.u32.u64 %0, t; }" : "=r"(a) : "l"(p));
    return a;
}
__device__ __forceinline__ uint32_t pack2bf(float lo, float hi) {
    uint32_t r;   // r = {hi16(hi) | lo16(lo)}: low address elem in low bits
    asm("cvt.rn.bf16x2.f32 %0, %1, %2;" : "=r"(r) : "f"(hi), "f"(lo));
    return r;
}
__device__ __forceinline__ void ldsm4(uint32_t* r, uint32_t addr) {
    asm volatile("ldmatrix.sync.aligned.m8n8.x4.shared.b16 {%0,%1,%2,%3}, [%4];"
                 : "=r"(r[0]), "=r"(r[1]), "=r"(r[2]), "=r"(r[3]) : "r"(addr));
}
__device__ __forceinline__ void mma16816(float* c, const uint32_t* a, const uint32_t* b) {
    asm volatile("mma.sync.aligned.m16n8k16.row.col.f32.bf16.bf16.f32 "
                 "{%0,%1,%2,%3}, {%4,%5,%6,%7}, {%8,%9}, {%0,%1,%2,%3};"
                 : "+f"(c[0]), "+f"(c[1]), "+f"(c[2]), "+f"(c[3])
                 : "r"(a[0]), "r"(a[1]), "r"(a[2]), "r"(a[3]), "r"(b[0]), "r"(b[1]));
}
__device__ __forceinline__ void cpasync16(uint32_t saddr, const void* gptr) {
    asm volatile("cp.async.cg.shared.global [%0], [%1], 16;" :: "r"(saddr), "l"(gptr) : "memory");
}

// ---------------- K1: prep — Wsum split into bf16 hi/lo; vb table ----------------
__global__ void prep_kernel(const float* __restrict__ Wa_w, const float* __restrict__ Wa_b,
                            const float* __restrict__ Ua_w, const float* __restrict__ Ua_b,
                            const float* __restrict__ Va_w) {
    int i = blockIdx.x * blockDim.x + threadIdx.x;
    if (i < HH * HH) {
        float w = Wa_w[i] + Ua_w[i];
        __nv_bfloat16 h = __float2bfloat16_rn(w);
        g_Wh[i] = h;
        g_Wl[i] = __float2bfloat16_rn(w - __bfloat162float(h));
    }
    if (i < HH) {
        float b = Wa_b[i] + Ua_b[i];
        g_vb[i] = make_float2(Va_w[i], b * TWO_LOG2E);
    }
}

// ---------------- K2: fused score GEMM on legacy tensor cores ----------------
// score[m] = sum_o v[o] * tanh(bsum[o] + sum_k X[m,k]*Wsum[o,k])
// CTA: M=128, 4 passes of N=128, K=512 in 8 chunks of 64.
// Stage: Ah(16K) Al(16K) Bh(16K) Bl(16K) = 64KB, double buffered.

#define STAGE_SZ 65536
#define SM_DYN   (2*STAGE_SZ + 1024)

__device__ __forceinline__ void ldgA(const float* __restrict__ X, size_t m_base,
                                     int kc, float4* xr, int tid) {
#pragma unroll
    for (int i = 0; i < 8; i++) {
        int g  = tid + i * 256;         // 0..2047 float4 units (128 rows x 16)
        int m  = g >> 4;
        int k4 = (g & 15) << 2;
        xr[i] = *(const float4*)(X + (m_base + m) * HH + kc * 64 + k4);
    }
}

__device__ __forceinline__ void stA(uint32_t abase, int buf, const float4* xr, int tid) {
    const uint32_t Ah = abase + buf * STAGE_SZ;
    const uint32_t Al = Ah + 16384;
#pragma unroll
    for (int i = 0; i < 8; i++) {
        int g  = tid + i * 256;
        int m  = g >> 4;
        int k4 = (g & 15) << 2;
        float4 x = xr[i];
        uint32_t h0 = pack2bf(x.x, x.y);
        uint32_t h1 = pack2bf(x.z, x.w);
        float rx = x.x - __uint_as_float(h0 << 16);
        float ry = x.y - __uint_as_float(h0 & 0xffff0000u);
        float rz = x.z - __uint_as_float(h1 << 16);
        float rw = x.w - __uint_as_float(h1 & 0xffff0000u);
        uint32_t l0 = pack2bf(rx, ry);
        uint32_t l1 = pack2bf(rz, rw);
        uint32_t off = SW128(m * 128 + k4 * 2);
        asm volatile("st.shared.v2.b32 [%0], {%1,%2};" :: "r"(Ah + off), "r"(h0), "r"(h1) : "memory");
        asm volatile("st.shared.v2.b32 [%0], {%1,%2};" :: "r"(Al + off), "r"(l0), "r"(l1) : "memory");
    }
}

__device__ __forceinline__ void cpB(uint32_t abase, int buf, int nb, int kc, int tid) {
    const uint32_t Bh = abase + buf * STAGE_SZ + 32768;
    const uint32_t Bl = Bh + 16384;
    const char* gh = (const char*)g_Wh;
    const char* gl = (const char*)g_Wl;
#pragma unroll
    for (int i = 0; i < 4; i++) {
        int u  = tid + i * 256;         // 0..1023 (128 o-rows x 8 16B units)
        int o  = u >> 3;
        int uu = u & 7;
        size_t gbyte = ((size_t)(nb * 128 + o) * 64 + kc * 8 + uu) * 16;
        uint32_t off = SW128(o * 128 + uu * 16);
        cpasync16(Bh + off, gh + gbyte);
        cpasync16(Bl + off, gl + gbyte);
    }
}

__global__ __launch_bounds__(256, 1)
void score_kernel(const float* __restrict__ X) {
    extern __shared__ __align__(1024) char smem[];
    __shared__ float score_sm[128];
    const uint32_t sb = smem_u32(smem);
    const uint32_t abase = (sb + 1023u) & ~1023u;   // 1024-aligned stage base
    const int tid  = threadIdx.x;
    const int lane = tid & 31;
    const int wid  = tid >> 5;
    const int wm   = wid & 3;                        // m-warp 0..3
    const int wn   = wid >> 2;                       // n-warp 0..1
    const size_t m_base = (size_t)blockIdx.x * 128;

    if (tid < 128) score_sm[tid] = 0.0f;

    // per-thread ldmatrix offset bases (within a 128B-row swizzled tile)
    const uint32_t xw = (uint32_t)((lane & 7) << 4);
    uint32_t aoff[2];
#pragma unroll
    for (int mf = 0; mf < 2; mf++) {
        int mrow = wm * 32 + mf * 16 + (lane & 15);
        aoff[mf] = mrow * 128 + ((lane >> 4) << 4);
    }
    uint32_t boff[4];
#pragma unroll
    for (int nf = 0; nf < 4; nf++) {
        int nrow = wn * 64 + nf * 16 + (lane & 7) + ((lane >> 4) << 3);
        boff[nf] = nrow * 128 + (((lane >> 3) & 1) << 4);
    }

    float4 xr[8];
    float c[2][8][4];

    for (int nb = 0; nb < 4; nb++) {
#pragma unroll
        for (int mf = 0; mf < 2; mf++)
#pragma unroll
            for (int j = 0; j < 8; j++)
#pragma unroll
                for (int q = 0; q < 4; q++) c[mf][j][q] = 0.0f;

        // stage chunk 0 into buf 0
        ldgA(X, m_base, 0, xr, tid);
        cpB(abase, 0, nb, 0, tid);
        stA(abase, 0, xr, tid);
        asm volatile("cp.async.commit_group;");
        asm volatile("cp.async.wait_group 0;" ::: "memory");
        __syncthreads();

        for (int kc = 0; kc < 8; kc++) {
            const int buf = kc & 1;
            if (kc < 7) {
                ldgA(X, m_base, kc + 1, xr, tid);
                cpB(abase, buf ^ 1, nb, kc + 1, tid);
                asm volatile("cp.async.commit_group;");
            }
            const uint32_t Ah = abase + buf * STAGE_SZ;
            const uint32_t Al = Ah + 16384;
            const uint32_t Bh = Ah + 32768;
            const uint32_t Bl = Ah + 49152;
#pragma unroll
            for (int k16 = 0; k16 < 4; k16++) {
                uint32_t ah[2][4], al[2][4], bb[4][4];
#pragma unroll
                for (int mf = 0; mf < 2; mf++) {
                    ldsm4(ah[mf], Ah + ((aoff[mf] + k16 * 32) ^ xw));
                    ldsm4(al[mf], Al + ((aoff[mf] + k16 * 32) ^ xw));
                }
#pragma unroll
                for (int nf = 0; nf < 4; nf++)
                    ldsm4(bb[nf], Bh + ((boff[nf] + k16 * 32) ^ xw));
#pragma unroll
                for (int mf = 0; mf < 2; mf++)
#pragma unroll
                    for (int nf = 0; nf < 4; nf++) {
                        mma16816(c[mf][2 * nf],     ah[mf], &bb[nf][0]);
                        mma16816(c[mf][2 * nf + 1], ah[mf], &bb[nf][2]);
                    }
#pragma unroll
                for (int mf = 0; mf < 2; mf++)
#pragma unroll
                    for (int nf = 0; nf < 4; nf++) {
                        mma16816(c[mf][2 * nf],     al[mf], &bb[nf][0]);
                        mma16816(c[mf][2 * nf + 1], al[mf], &bb[nf][2]);
                    }
#pragma unroll
                for (int nf = 0; nf < 4; nf++)
                    ldsm4(bb[nf], Bl + ((boff[nf] + k16 * 32) ^ xw));
#pragma unroll
                for (int mf = 0; mf < 2; mf++)
#pragma unroll
                    for (int nf = 0; nf < 4; nf++) {
                        mma16816(c[mf][2 * nf],     ah[mf], &bb[nf][0]);
                        mma16816(c[mf][2 * nf + 1], ah[mf], &bb[nf][2]);
                    }
            }
            if (kc < 7) {
                stA(abase, buf ^ 1, xr, tid);
                asm volatile("cp.async.wait_group 0;" ::: "memory");
            }
            __syncthreads();
        }

        // fused epilogue: score += v[o]*tanh(acc + b[o])
        const int quad = lane & 3;
#pragma unroll
        for (int mf = 0; mf < 2; mf++) {
            float s0 = 0.0f, s1 = 0.0f;
#pragma unroll
            for (int j = 0; j < 8; j++) {
#pragma unroll
                for (int col = 0; col < 2; col++) {
                    int o = nb * 128 + wn * 64 + j * 8 + quad * 2 + col;
                    float2 vbv = __ldg(&g_vb[o]);
                    float x0 = fmaf(c[mf][j][col],     TWO_LOG2E, vbv.y);
                    float x1 = fmaf(c[mf][j][col + 2], TWO_LOG2E, vbv.y);
                    float e0, e1, r0, r1;
                    asm("ex2.approx.f32 %0, %1;" : "=f"(e0) : "f"(x0));
                    asm("ex2.approx.f32 %0, %1;" : "=f"(e1) : "f"(x1));
                    asm("rcp.approx.f32 %0, %1;" : "=f"(r0) : "f"(e0 + 1.0f));
                    asm("rcp.approx.f32 %0, %1;" : "=f"(r1) : "f"(e1 + 1.0f));
                    s0 += vbv.x - 2.0f * vbv.x * r0;   // v*tanh
                    s1 += vbv.x - 2.0f * vbv.x * r1;
                }
            }
            s0 += __shfl_xor_sync(0xffffffffu, s0, 1);
            s0 += __shfl_xor_sync(0xffffffffu, s0, 2);
            s1 += __shfl_xor_sync(0xffffffffu, s1, 1);
            s1 += __shfl_xor_sync(0xffffffffu, s1, 2);
            if (quad == 0) {
                int r = wm * 32 + mf * 16 + (lane >> 2);
                atomicAdd(&score_sm[r], s0);
                atomicAdd(&score_sm[r + 8], s1);
            }
        }
        __syncthreads();
    }

    if (tid < 128) g_score[m_base + tid] = score_sm[tid];
}

// ---------------- K3: per-batch softmax over T ----------------
__global__ void softmax_kernel(float* __restrict__ aw_out) {
    __shared__ float sh[TT];
    __shared__ float red[256];
    const int b = blockIdx.x;
    const int tid = threadIdx.x;
    const float* s = g_score + (size_t)b * TT;

    float mx = -1e30f;
    for (int t = tid; t < TT; t += 256) {
        float v = s[t];
        sh[t] = v;
        mx = fmaxf(mx, v);
    }
    red[tid] = mx;
    __syncthreads();
    for (int o = 128; o > 0; o >>= 1) {
        if (tid < o) red[tid] = fmaxf(red[tid], red[tid + o]);
        __syncthreads();
    }
    mx = red[0];
    __syncthreads();

    float sum = 0.0f;
    for (int t = tid; t < TT; t += 256) {
        float e = __expf(sh[t] - mx);
        sh[t] = e;
        sum += e;
    }
    red[tid] = sum;
    __syncthreads();
    for (int o = 128; o > 0; o >>= 1) {
        if (tid < o) red[tid] += red[tid + o];
        __syncthreads();
    }
    float inv = 1.0f / red[0];
    for (int t = tid; t < TT; t += 256)
        aw_out[(size_t)b * TT + t] = sh[t] * inv;
}

// ---------------- K4: context partials over T-quarters + combine ----------------
__global__ void context_part_kernel(const float* __restrict__ X,
                                    const float* __restrict__ aw) {
    const int blk = blockIdx.x;          // b*16 + hb*4 + tb
    const int b  = blk >> 4;
    const int hb = (blk >> 2) & 3;
    const int tb = blk & 3;
    const int h  = hb * 128 + threadIdx.x;
    const float* xp = X + (size_t)b * TT * HH + (size_t)tb * 512 * HH + h;
    const float* a  = aw + (size_t)b * TT + tb * 512;

    float acc = 0.0f;
#pragma unroll 8
    for (int t = 0; t < 512; t++)
        acc += a[t] * xp[(size_t)t * HH];

    g_cpart[((size_t)tb * BB + b) * HH + h] = acc;
}

__global__ void context_combine_kernel(float* __restrict__ ctx) {
    int i = blockIdx.x * blockDim.x + threadIdx.x;
    ctx[i] = g_cpart[i] + g_cpart[BB * HH + i]
           + g_cpart[2 * BB * HH + i] + g_cpart[3 * BB * HH + i];
}

// ---------------- launch ----------------
extern "C" void kernel_launch(void* const* d_in, const int* in_sizes, int n_in,
                              void* d_out, int out_size) {
    const float* X    = (const float*)d_in[0];
    const float* Wa_w = (const float*)d_in[1];
    const float* Wa_b = (const float*)d_in[2];
    const float* Ua_w = (const float*)d_in[3];
    const float* Ua_b = (const float*)d_in[4];
    const float* Va_w = (const float*)d_in[5];
    // d_in[6] (Va_b) unused: softmax is shift-invariant.
    (void)in_sizes; (void)n_in; (void)out_size;

    float* out = (float*)d_out;
    float* ctx = out;                 // [B, H]
    float* aw  = out + BB * HH;       // [B, T]

    cudaFuncSetAttribute(score_kernel, cudaFuncAttributeMaxDynamicSharedMemorySize, SM_DYN);

    prep_kernel<<<(HH * HH + 255) / 256, 256>>>(Wa_w, Wa_b, Ua_w, Ua_b, Va_w);
    score_kernel<<<MM / 128, 256, SM_DYN>>>(X);
    softmax_kernel<<<BB, 256>>>(aw);
    context_part_kernel<<<BB * 16, 128>>>(X, aw);
    context_combine_kernel<<<BB * HH / 256, 256>>>(ctx);
}